// round 12
// baseline (speedup 1.0000x reference)
#include <cuda_runtime.h>
#include <cuda_fp16.h>
#include <cstdint>

// Problem constants
#define SB   1024
#define DD   64
#define BB   8
#define HH   8
#define CC   21
#define OUT_ELEMS (BB*HH*SB*DD)
#define KPU  36      // smem chunk pitch in uints (72 halves = 144B) -> LDSM conflict-free

// ---------------------------------------------------------------------------
// Scratch 1: fragment-tiled bias/e, [bh(64)][qg(64)][kgrp(128)][lane(32)] uint2.
// Scratch 2: fp16 K and V, [2][bh(64)][s(1024)][d(64)].
// Scratch 3: per-row softmax reciprocals 1/l, [bh(64)][row(1024)].
// ---------------------------------------------------------------------------
__device__ uint4  g_scr[64ull * 64 * 2048];          // 128 MiB
__device__ __half g_kv[2ull * 64 * 1024 * 64];       // 16.8 MiB
__device__ float  g_linv[64 * 1024];                 // 256 KiB

__device__ __forceinline__ unsigned packh2(float x, float y) {
    __half2 h = __float22half2_rn(make_float2(x, y));
    return *reinterpret_cast<unsigned*>(&h);
}

__device__ __forceinline__ void mma_f16(float c[4], const unsigned a[4],
                                        unsigned b0, unsigned b1) {
    asm volatile(
        "mma.sync.aligned.m16n8k16.row.col.f32.f16.f16.f32 "
        "{%0,%1,%2,%3}, {%4,%5,%6,%7}, {%8,%9}, {%0,%1,%2,%3};\n"
        : "+f"(c[0]), "+f"(c[1]), "+f"(c[2]), "+f"(c[3])
        : "r"(a[0]), "r"(a[1]), "r"(a[2]), "r"(a[3]), "r"(b0), "r"(b1));
}

__device__ __forceinline__ void ldsm4(unsigned r[4], unsigned saddr) {
    asm volatile(
        "ldmatrix.sync.aligned.m8n8.x4.shared.b16 {%0,%1,%2,%3}, [%4];\n"
        : "=r"(r[0]), "=r"(r[1]), "=r"(r[2]), "=r"(r[3]) : "r"(saddr));
}

__device__ __forceinline__ void ldsm4t(unsigned r[4], unsigned saddr) {
    asm volatile(
        "ldmatrix.sync.aligned.m8n8.x4.trans.shared.b16 {%0,%1,%2,%3}, [%4];\n"
        : "=r"(r[0]), "=r"(r[1]), "=r"(r[2]), "=r"(r[3]) : "r"(saddr));
}

__device__ __forceinline__ void cpa16(unsigned sdst, const void* gsrc) {
    asm volatile("cp.async.cg.shared.global [%0], [%1], 16;\n"
                 :: "r"(sdst), "l"(gsrc));
}
#define CPA_COMMIT() asm volatile("cp.async.commit_group;\n")
#define CPA_WAIT1()  asm volatile("cp.async.wait_group 1;\n")
#define CPA_WAIT0()  asm volatile("cp.async.wait_group 0;\n")

// ---------------------------------------------------------------------------
// Kernel 0: K/V fp32 -> fp16 relayout (streaming loads, high occupancy).
// ---------------------------------------------------------------------------
__global__ __launch_bounds__(256) void k_cvt(
    const float* __restrict__ K, const float* __restrict__ V)
{
    unsigned i = blockIdx.x * 256u + threadIdx.x;
    const float4* src = (i < 1048576u)
        ? reinterpret_cast<const float4*>(K)
        : reinterpret_cast<const float4*>(V) - 1048576;
    float4 v = __ldcs(&src[i]);
    uint2 st;
    st.x = packh2(v.x, v.y);
    st.y = packh2(v.z, v.w);
    reinterpret_cast<uint2*>(g_kv)[i] = st;
}

// ---------------------------------------------------------------------------
// Kernel 1: bias = sum_c dtw*W + b - 4; masked -> -60000. Fragment-tiled out.
// ---------------------------------------------------------------------------
__global__ __launch_bounds__(256) void k_bias(
    const float* __restrict__ dtw, const int* __restrict__ mask,
    const float* __restrict__ W, const float* __restrict__ bvec)
{
    __shared__ float Ws[HH * CC];
    __shared__ float bs[HH];
    int t = threadIdx.x;
    if (t < HH * CC) Ws[t] = W[t];
    if (t < HH)      bs[t] = bvec[t] - 4.0f;
    __syncthreads();

    unsigned idx = blockIdx.x * 256u + (unsigned)t;  // [bb:3][qg:6][r:3][k4:8]
    int k4 = idx & 255;
    int r  = (idx >> 8) & 7;
    int qg = (idx >> 11) & 63;
    int bb = idx >> 17;
    int qlo = qg * 16 + r;

    const float4* dp = reinterpret_cast<const float4*>(dtw)
                       + ((size_t)(bb * CC) * SB + qlo) * 256 + k4;
    const int4* mp = reinterpret_cast<const int4*>(mask)
                     + ((size_t)bb * SB + qlo) * 256 + k4;
    int4 mlo = mp[0];
    int4 mhi = mp[8 * 256];

    float4 a[HH];
    uint2  lo[HH];

#pragma unroll
    for (int h = 0; h < HH; h++) a[h] = make_float4(bs[h], bs[h], bs[h], bs[h]);
#pragma unroll
    for (int c = 0; c < CC; c++) {
        float4 d = __ldcs(dp + (size_t)c * (SB * 256));
#pragma unroll
        for (int h = 0; h < HH; h++) {
            float w = Ws[h * CC + c];
            a[h].x += w * d.x; a[h].y += w * d.y;
            a[h].z += w * d.z; a[h].w += w * d.w;
        }
    }
#pragma unroll
    for (int h = 0; h < HH; h++) {
        lo[h].x = packh2(mlo.x ? a[h].x : -60000.f, mlo.y ? a[h].y : -60000.f);
        lo[h].y = packh2(mlo.z ? a[h].z : -60000.f, mlo.w ? a[h].w : -60000.f);
    }

#pragma unroll
    for (int h = 0; h < HH; h++) a[h] = make_float4(bs[h], bs[h], bs[h], bs[h]);
#pragma unroll
    for (int c = 0; c < CC; c++) {
        float4 d = __ldcs(dp + (size_t)c * (SB * 256) + 8 * 256);
#pragma unroll
        for (int h = 0; h < HH; h++) {
            float w = Ws[h * CC + c];
            a[h].x += w * d.x; a[h].y += w * d.y;
            a[h].z += w * d.z; a[h].w += w * d.w;
        }
    }

    size_t base4 = ((size_t)(bb * HH) * 64 + qg) * 2048
                 + (size_t)(k4 >> 1) * 16 + r * 2 + (k4 & 1);
#pragma unroll
    for (int h = 0; h < HH; h++) {
        uint4 v;
        v.x = lo[h].x;
        v.y = packh2(mhi.x ? a[h].x : -60000.f, mhi.y ? a[h].y : -60000.f);
        v.z = lo[h].y;
        v.w = packh2(mhi.z ? a[h].z : -60000.f, mhi.w ? a[h].w : -60000.f);
        g_scr[base4 + (size_t)h * (64 * 2048)] = v;
    }
}

// ---------------------------------------------------------------------------
// Kernel 2: pass 1 — e = exp(QK/8 + bias') -> scratch (fp16); 1/l -> g_linv.
// 4 CTAs/SM -> grid 512 fits in ONE wave.
// ---------------------------------------------------------------------------
__global__ __launch_bounds__(256, 4) void k_pass1(
    const float* __restrict__ Q)
{
    __shared__ unsigned Bu[2][128 * KPU];

    const int tid  = threadIdx.x;
    const int warp = tid >> 5;
    const int lane = tid & 31;
    const int g    = lane >> 2;
    const int tg   = lane & 3;

    const int bh = blockIdx.x >> 3;
    const int q8 = blockIdx.x & 7;
    const int qg = q8 * 8 + warp;
    const int wb = warp * 16;

    const float*  Qg = Q + ((size_t)bh * SB + q8 * 128 + wb) * DD;
    const __half* Kh = g_kv + (size_t)bh * (SB * DD);
    uint2* scrW  = reinterpret_cast<uint2*>(g_scr)
                 + ((size_t)bh * 64 + qg) * 4096 + lane;

    const unsigned sB0 = (unsigned)__cvta_generic_to_shared(&Bu[0][0]);
    const unsigned sB1 = sB0 + 128 * KPU * 4;

    auto load_chunk = [&](unsigned sbuf, const __half* src) {
#pragma unroll
        for (int j = 0; j < 4; j++) {
            int i = tid + j * 256;
            int r = i >> 3, u = i & 7;
            cpa16(sbuf + r * (KPU * 4) + u * 16, src + r * 64 + u * 8);
        }
    };

    unsigned aq[4][4];
#pragma unroll
    for (int ks = 0; ks < 4; ks++) {
        float2 v0 = *reinterpret_cast<const float2*>(Qg + g * DD + ks * 16 + tg * 2);
        float2 v1 = *reinterpret_cast<const float2*>(Qg + (g + 8) * DD + ks * 16 + tg * 2);
        float2 v2 = *reinterpret_cast<const float2*>(Qg + g * DD + ks * 16 + 8 + tg * 2);
        float2 v3 = *reinterpret_cast<const float2*>(Qg + (g + 8) * DD + ks * 16 + 8 + tg * 2);
        aq[ks][0] = packh2(v0.x * 0.125f, v0.y * 0.125f);
        aq[ks][1] = packh2(v1.x * 0.125f, v1.y * 0.125f);
        aq[ks][2] = packh2(v2.x * 0.125f, v2.y * 0.125f);
        aq[ks][3] = packh2(v3.x * 0.125f, v3.y * 0.125f);
    }

    const unsigned laneK = (lane & 7) * (KPU * 4) + (lane >> 3) * 16;
    float l0 = 0.f, l1 = 0.f;

    load_chunk(sB0, Kh);
    CPA_COMMIT();

    for (int ch = 0; ch < 8; ++ch) {
        if (ch < 7) {
            load_chunk((ch & 1) ? sB0 : sB1, Kh + (size_t)(ch + 1) * 8192);
            CPA_COMMIT();
            CPA_WAIT1();
        } else {
            CPA_WAIT0();
        }
        __syncthreads();

        const unsigned sb = (ch & 1) ? sB1 : sB0;
        uint2 bf[4];
#pragma unroll
        for (int p = 0; p < 4; p++) bf[p] = scrW[(ch * 16 + p) * 32];

#pragma unroll
        for (int t8 = 0; t8 < 16; t8++) {
            uint2 ef = bf[t8 & 3];
            if (t8 < 12) bf[t8 & 3] = scrW[(ch * 16 + t8 + 4) * 32];

            unsigned qv[4], qw[4];
            ldsm4(qv, sb + t8 * (8 * KPU * 4) + laneK);
            ldsm4(qw, sb + t8 * (8 * KPU * 4) + laneK + 64);
            float c4[4] = {0.f, 0.f, 0.f, 0.f};
            mma_f16(c4, aq[0], qv[0], qv[1]);
            mma_f16(c4, aq[1], qv[2], qv[3]);
            mma_f16(c4, aq[2], qw[0], qw[1]);
            mma_f16(c4, aq[3], qw[2], qw[3]);

            float2 f0 = __half22float2(*reinterpret_cast<__half2*>(&ef.x));
            float2 f1 = __half22float2(*reinterpret_cast<__half2*>(&ef.y));
            float e0 = __expf(c4[0] + f0.x);
            float e1 = __expf(c4[1] + f0.y);
            float e2 = __expf(c4[2] + f1.x);
            float e3 = __expf(c4[3] + f1.y);
            l0 += e0 + e1;
            l1 += e2 + e3;
            uint2 st;
            st.x = packh2(e0, e1);
            st.y = packh2(e2, e3);
            scrW[(ch * 16 + t8) * 32] = st;
        }
        __syncthreads();
    }

    l0 += __shfl_xor_sync(0xffffffffu, l0, 1);
    l0 += __shfl_xor_sync(0xffffffffu, l0, 2);
    l1 += __shfl_xor_sync(0xffffffffu, l1, 1);
    l1 += __shfl_xor_sync(0xffffffffu, l1, 2);

    if (tg == 0) {
        g_linv[bh * SB + qg * 16 + g]     = 1.f / l0;
        g_linv[bh * SB + qg * 16 + g + 8] = 1.f / l1;
    }
}

// ---------------------------------------------------------------------------
// Kernel 3: pass 2 — attention = e/l with warp-private smem staging for
// fully-coalesced row stores; O = (sum e*V)/l via mma. 64-key V chunks.
// smem = 18.4 KB (V dbl buf) + 18.4 KB (staging) -> 4 CTAs/SM, one wave.
// ---------------------------------------------------------------------------
#define EPITCH 36    // staging row pitch in uints: banks 4g+tg -> conflict-free

__global__ __launch_bounds__(256, 4) void k_pass2(
    float* __restrict__ out)
{
    __shared__ unsigned Bu[2][64 * KPU];       // V chunks (64 keys)
    __shared__ unsigned Est[8 * 16 * EPITCH];  // per-warp e staging (16x64 fp16)

    const int tid  = threadIdx.x;
    const int warp = tid >> 5;
    const int lane = tid & 31;
    const int g    = lane >> 2;
    const int tg   = lane & 3;

    const int bh = blockIdx.x >> 3;
    const int q8 = blockIdx.x & 7;
    const int qg = q8 * 8 + warp;
    const int wb = warp * 16;

    const __half* Vh = g_kv + (size_t)(64 + bh) * (SB * DD);
    float* attnW = out + OUT_ELEMS + ((size_t)bh * SB + q8 * 128 + wb) * SB;
    float* outW  = out + ((size_t)bh * SB + q8 * 128 + wb) * DD;
    uint2* scrW  = reinterpret_cast<uint2*>(g_scr)
                 + ((size_t)bh * 64 + qg) * 4096 + lane;

    const float r0 = g_linv[bh * SB + qg * 16 + g];
    const float r1 = g_linv[bh * SB + qg * 16 + g + 8];

    const unsigned sB0 = (unsigned)__cvta_generic_to_shared(&Bu[0][0]);
    const unsigned sB1 = sB0 + 64 * KPU * 4;
    unsigned* Ew = Est + warp * (16 * EPITCH);

    auto load_chunk = [&](unsigned sbuf, const __half* src) {
#pragma unroll
        for (int j = 0; j < 2; j++) {          // 64 rows x 8 uint4 = 512
            int i = tid + j * 256;
            int r = i >> 3, u = i & 7;
            cpa16(sbuf + r * (KPU * 4) + u * 16, src + r * 64 + u * 8);
        }
    };

    float oc[8][4];
#pragma unroll
    for (int dt = 0; dt < 8; dt++)
#pragma unroll
        for (int j = 0; j < 4; j++) oc[dt][j] = 0.f;

    const unsigned laneV = ((lane & 7) + 8 * ((lane >> 3) & 1)) * (KPU * 4)
                         + (lane >> 4) * 16;
    const int half = lane >> 4;       // 0: rows 0..7, 1: rows 8..15 (readback)
    const int li   = lane & 15;       // column slot in readback

    load_chunk(sB0, Vh);
    CPA_COMMIT();

    for (int ch = 0; ch < 16; ++ch) {
        if (ch < 15) {
            load_chunk((ch & 1) ? sB0 : sB1, Vh + (size_t)(ch + 1) * 4096);
            CPA_COMMIT();
            CPA_WAIT1();
        } else {
            CPA_WAIT0();
        }
        __syncthreads();

        const unsigned sb = (ch & 1) ? sB1 : sB0;
        uint2 pf[2][2];
#pragma unroll
        for (int p = 0; p < 2; p++) {
            pf[p][0] = __ldcs(&scrW[(ch * 8 + 2 * p) * 32]);
            pf[p][1] = __ldcs(&scrW[(ch * 8 + 2 * p + 1) * 32]);
        }

#pragma unroll
        for (int kg = 0; kg < 4; kg++) {       // 4 x 16-key groups per chunk
            uint2 ef0 = pf[kg & 1][0];
            uint2 ef1 = pf[kg & 1][1];
            if (kg < 2) {
                pf[kg & 1][0] = __ldcs(&scrW[(ch * 8 + 2 * kg + 4) * 32]);
                pf[kg & 1][1] = __ldcs(&scrW[(ch * 8 + 2 * kg + 5) * 32]);
            }
            unsigned ap[4] = {ef0.x, ef0.y, ef1.x, ef1.y};

            // stage e to warp-private smem (banks 4g+tg -> conflict-free)
            Ew[g * EPITCH + kg * 8 + tg]           = ef0.x;
            Ew[g * EPITCH + kg * 8 + 4 + tg]       = ef1.x;
            Ew[(g + 8) * EPITCH + kg * 8 + tg]     = ef0.y;
            Ew[(g + 8) * EPITCH + kg * 8 + 4 + tg] = ef1.y;

#pragma unroll
            for (int dp2 = 0; dp2 < 4; dp2++) {
                unsigned v[4];
                ldsm4t(v, sb + kg * (16 * KPU * 4) + laneV + dp2 * 32);
                mma_f16(oc[dp2 * 2],     ap, v[0], v[1]);
                mma_f16(oc[dp2 * 2 + 1], ap, v[2], v[3]);
            }
        }

        __syncwarp();
        // coalesced attention stores: 2 rows x 256B per STG pass
#pragma unroll
        for (int rr = 0; rr < 8; rr++) {
            float sc_lo = __shfl_sync(0xffffffffu, r0, rr * 4);
            float sc_hi = __shfl_sync(0xffffffffu, r1, rr * 4);
            float sc  = half ? sc_hi : sc_lo;
            int   row = rr + half * 8;
            uint2 d = *reinterpret_cast<uint2*>(&Ew[row * EPITCH + li * 2]);
            float2 fa = __half22float2(*reinterpret_cast<__half2*>(&d.x));
            float2 fb = __half22float2(*reinterpret_cast<__half2*>(&d.y));
            __stcs(reinterpret_cast<float4*>(attnW + (size_t)row * SB + ch * 64 + li * 4),
                   make_float4(fa.x * sc, fa.y * sc, fb.x * sc, fb.y * sc));
        }
        __syncthreads();
    }

#pragma unroll
    for (int dt = 0; dt < 8; dt++) {
        int col = dt * 8 + tg * 2;
        *reinterpret_cast<float2*>(outW + (size_t)g * DD + col) =
            make_float2(oc[dt][0] * r0, oc[dt][1] * r0);
        *reinterpret_cast<float2*>(outW + (size_t)(g + 8) * DD + col) =
            make_float2(oc[dt][2] * r1, oc[dt][3] * r1);
    }
}

// ---------------------------------------------------------------------------
extern "C" void kernel_launch(void* const* d_in, const int* in_sizes, int n_in,
                              void* d_out, int out_size)
{
    const float* Q    = (const float*)d_in[0];
    const float* K    = (const float*)d_in[1];
    const float* V    = (const float*)d_in[2];
    const float* dtw  = (const float*)d_in[3];
    const int*   mask = (const int*)d_in[4];
    const float* W    = (const float*)d_in[5];
    const float* bvec = (const float*)d_in[6];
    float*       out  = (float*)d_out;

    k_cvt<<<8192, 256>>>(K, V);
    k_bias<<<4096, 256>>>(dtw, mask, W, bvec);
    k_pass1<<<BB * HH * (SB / 128), 256>>>(Q);
    k_pass2<<<BB * HH * (SB / 128), 256>>>(out);
}

// round 14
// speedup vs baseline: 1.1677x; 1.1677x over previous
#include <cuda_runtime.h>
#include <cuda_fp16.h>
#include <cstdint>

// Problem constants
#define SB   1024
#define DD   64
#define BB   8
#define HH   8
#define CC   21
#define OUT_ELEMS (BB*HH*SB*DD)
#define KPU  36      // smem chunk pitch in uints (72 halves = 144B) -> LDSM conflict-free

// ---------------------------------------------------------------------------
// Scratch 1: fragment-tiled bias/e, [bh(64)][qg(64)][kgrp(128)][lane(32)] uint2.
// Scratch 2: fp16 K and V, [2][bh(64)][s(1024)][d(64)].
// Scratch 3: per-row softmax reciprocals 1/l, [bh(64)][row(1024)].
// ---------------------------------------------------------------------------
__device__ uint4  g_scr[64ull * 64 * 2048];          // 128 MiB
__device__ __half g_kv[2ull * 64 * 1024 * 64];       // 16.8 MiB
__device__ float  g_linv[64 * 1024];                 // 256 KiB

// PDL intrinsics (no allocations, graph-capturable)
#define GDC_LAUNCH() asm volatile("griddepcontrol.launch_dependents;")
#define GDC_WAIT()   asm volatile("griddepcontrol.wait;" ::: "memory")

__device__ __forceinline__ unsigned packh2(float x, float y) {
    __half2 h = __float22half2_rn(make_float2(x, y));
    return *reinterpret_cast<unsigned*>(&h);
}

__device__ __forceinline__ void mma_f16(float c[4], const unsigned a[4],
                                        unsigned b0, unsigned b1) {
    asm volatile(
        "mma.sync.aligned.m16n8k16.row.col.f32.f16.f16.f32 "
        "{%0,%1,%2,%3}, {%4,%5,%6,%7}, {%8,%9}, {%0,%1,%2,%3};\n"
        : "+f"(c[0]), "+f"(c[1]), "+f"(c[2]), "+f"(c[3])
        : "r"(a[0]), "r"(a[1]), "r"(a[2]), "r"(a[3]), "r"(b0), "r"(b1));
}

__device__ __forceinline__ void ldsm4(unsigned r[4], unsigned saddr) {
    asm volatile(
        "ldmatrix.sync.aligned.m8n8.x4.shared.b16 {%0,%1,%2,%3}, [%4];\n"
        : "=r"(r[0]), "=r"(r[1]), "=r"(r[2]), "=r"(r[3]) : "r"(saddr));
}

__device__ __forceinline__ void ldsm4t(unsigned r[4], unsigned saddr) {
    asm volatile(
        "ldmatrix.sync.aligned.m8n8.x4.trans.shared.b16 {%0,%1,%2,%3}, [%4];\n"
        : "=r"(r[0]), "=r"(r[1]), "=r"(r[2]), "=r"(r[3]) : "r"(saddr));
}

__device__ __forceinline__ void cpa16(unsigned sdst, const void* gsrc) {
    asm volatile("cp.async.cg.shared.global [%0], [%1], 16;\n"
                 :: "r"(sdst), "l"(gsrc));
}
#define CPA_COMMIT() asm volatile("cp.async.commit_group;\n")
#define CPA_WAIT1()  asm volatile("cp.async.wait_group 1;\n")
#define CPA_WAIT0()  asm volatile("cp.async.wait_group 0;\n")

// ---------------------------------------------------------------------------
// Kernel 0: K/V fp32 -> fp16 relayout. ONE wave (1184 CTAs, grid-stride);
// triggers dependents immediately so k_bias overlaps fully.
// ---------------------------------------------------------------------------
#define CVT_GRID 1184
__global__ __launch_bounds__(256) void k_cvt(
    const float* __restrict__ K, const float* __restrict__ V)
{
    GDC_LAUNCH();
    for (unsigned i = blockIdx.x * 256u + threadIdx.x; i < 2097152u;
         i += CVT_GRID * 256u) {
        const float4* src = (i < 1048576u)
            ? reinterpret_cast<const float4*>(K)
            : reinterpret_cast<const float4*>(V) - 1048576;
        float4 v = __ldcs(&src[i]);
        uint2 st;
        st.x = packh2(v.x, v.y);
        st.y = packh2(v.z, v.w);
        reinterpret_cast<uint2*>(g_kv)[i] = st;
    }
}

// ---------------------------------------------------------------------------
// Kernel 1: bias = sum_c dtw*W + b - 4; masked -> -60000. Fragment-tiled out.
// Launched with PSS (overlaps k_cvt; reads nothing k_cvt writes -> no wait).
// ---------------------------------------------------------------------------
__global__ __launch_bounds__(256) void k_bias(
    const float* __restrict__ dtw, const int* __restrict__ mask,
    const float* __restrict__ W, const float* __restrict__ bvec)
{
    __shared__ float Ws[HH * CC];
    __shared__ float bs[HH];
    int t = threadIdx.x;
    if (t < HH * CC) Ws[t] = W[t];
    if (t < HH)      bs[t] = bvec[t] - 4.0f;
    __syncthreads();

    unsigned idx = blockIdx.x * 256u + (unsigned)t;  // [bb:3][qg:6][r:3][k4:8]
    int k4 = idx & 255;
    int r  = (idx >> 8) & 7;
    int qg = (idx >> 11) & 63;
    int bb = idx >> 17;
    int qlo = qg * 16 + r;

    const float4* dp = reinterpret_cast<const float4*>(dtw)
                       + ((size_t)(bb * CC) * SB + qlo) * 256 + k4;
    const int4* mp = reinterpret_cast<const int4*>(mask)
                     + ((size_t)bb * SB + qlo) * 256 + k4;
    int4 mlo = mp[0];
    int4 mhi = mp[8 * 256];

    float4 a[HH];
    uint2  lo[HH];

#pragma unroll
    for (int h = 0; h < HH; h++) a[h] = make_float4(bs[h], bs[h], bs[h], bs[h]);
#pragma unroll
    for (int c = 0; c < CC; c++) {
        float4 d = __ldcs(dp + (size_t)c * (SB * 256));
#pragma unroll
        for (int h = 0; h < HH; h++) {
            float w = Ws[h * CC + c];
            a[h].x += w * d.x; a[h].y += w * d.y;
            a[h].z += w * d.z; a[h].w += w * d.w;
        }
    }
#pragma unroll
    for (int h = 0; h < HH; h++) {
        lo[h].x = packh2(mlo.x ? a[h].x : -60000.f, mlo.y ? a[h].y : -60000.f);
        lo[h].y = packh2(mlo.z ? a[h].z : -60000.f, mlo.w ? a[h].w : -60000.f);
    }

#pragma unroll
    for (int h = 0; h < HH; h++) a[h] = make_float4(bs[h], bs[h], bs[h], bs[h]);
#pragma unroll
    for (int c = 0; c < CC; c++) {
        float4 d = __ldcs(dp + (size_t)c * (SB * 256) + 8 * 256);
#pragma unroll
        for (int h = 0; h < HH; h++) {
            float w = Ws[h * CC + c];
            a[h].x += w * d.x; a[h].y += w * d.y;
            a[h].z += w * d.z; a[h].w += w * d.w;
        }
    }

    size_t base4 = ((size_t)(bb * HH) * 64 + qg) * 2048
                 + (size_t)(k4 >> 1) * 16 + r * 2 + (k4 & 1);
#pragma unroll
    for (int h = 0; h < HH; h++) {
        uint4 v;
        v.x = lo[h].x;
        v.y = packh2(mhi.x ? a[h].x : -60000.f, mhi.y ? a[h].y : -60000.f);
        v.z = lo[h].y;
        v.w = packh2(mhi.z ? a[h].z : -60000.f, mhi.w ? a[h].w : -60000.f);
        g_scr[base4 + (size_t)h * (64 * 2048)] = v;
    }
    GDC_LAUNCH();   // stores above are visible to pass1 after its wait
}

// ---------------------------------------------------------------------------
// Kernel 2: pass 1 — e = exp(QK/8 + bias') -> scratch (fp16); 1/l -> g_linv.
// PSS dependent of k_bias: Q-fragment prelude overlaps k_bias tail.
// ---------------------------------------------------------------------------
__global__ __launch_bounds__(256, 4) void k_pass1(
    const float* __restrict__ Q)
{
    __shared__ unsigned Bu[2][128 * KPU];

    const int tid  = threadIdx.x;
    const int warp = tid >> 5;
    const int lane = tid & 31;
    const int g    = lane >> 2;
    const int tg   = lane & 3;

    const int bh = blockIdx.x >> 3;
    const int q8 = blockIdx.x & 7;
    const int qg = q8 * 8 + warp;
    const int wb = warp * 16;

    const float*  Qg = Q + ((size_t)bh * SB + q8 * 128 + wb) * DD;
    const __half* Kh = g_kv + (size_t)bh * (SB * DD);
    uint2* scrW  = reinterpret_cast<uint2*>(g_scr)
                 + ((size_t)bh * 64 + qg) * 4096 + lane;

    const unsigned sB0 = (unsigned)__cvta_generic_to_shared(&Bu[0][0]);
    const unsigned sB1 = sB0 + 128 * KPU * 4;

    auto load_chunk = [&](unsigned sbuf, const __half* src) {
#pragma unroll
        for (int j = 0; j < 4; j++) {
            int i = tid + j * 256;
            int r = i >> 3, u = i & 7;
            cpa16(sbuf + r * (KPU * 4) + u * 16, src + r * 64 + u * 8);
        }
    };

    // prelude (independent of k_bias output): Q fragments, 1/8 folded
    unsigned aq[4][4];
#pragma unroll
    for (int ks = 0; ks < 4; ks++) {
        float2 v0 = *reinterpret_cast<const float2*>(Qg + g * DD + ks * 16 + tg * 2);
        float2 v1 = *reinterpret_cast<const float2*>(Qg + (g + 8) * DD + ks * 16 + tg * 2);
        float2 v2 = *reinterpret_cast<const float2*>(Qg + g * DD + ks * 16 + 8 + tg * 2);
        float2 v3 = *reinterpret_cast<const float2*>(Qg + (g + 8) * DD + ks * 16 + 8 + tg * 2);
        aq[ks][0] = packh2(v0.x * 0.125f, v0.y * 0.125f);
        aq[ks][1] = packh2(v1.x * 0.125f, v1.y * 0.125f);
        aq[ks][2] = packh2(v2.x * 0.125f, v2.y * 0.125f);
        aq[ks][3] = packh2(v3.x * 0.125f, v3.y * 0.125f);
    }

    GDC_WAIT();   // k_bias writes (bias scratch) now visible

    const unsigned laneK = (lane & 7) * (KPU * 4) + (lane >> 3) * 16;
    float l0 = 0.f, l1 = 0.f;

    load_chunk(sB0, Kh);
    CPA_COMMIT();

    for (int ch = 0; ch < 8; ++ch) {
        if (ch < 7) {
            load_chunk((ch & 1) ? sB0 : sB1, Kh + (size_t)(ch + 1) * 8192);
            CPA_COMMIT();
            CPA_WAIT1();
        } else {
            CPA_WAIT0();
        }
        __syncthreads();

        const unsigned sb = (ch & 1) ? sB1 : sB0;
        uint2 bf[4];
#pragma unroll
        for (int p = 0; p < 4; p++) bf[p] = scrW[(ch * 16 + p) * 32];

#pragma unroll
        for (int t8 = 0; t8 < 16; t8++) {
            uint2 ef = bf[t8 & 3];
            if (t8 < 12) bf[t8 & 3] = scrW[(ch * 16 + t8 + 4) * 32];

            unsigned qv[4], qw[4];
            ldsm4(qv, sb + t8 * (8 * KPU * 4) + laneK);
            ldsm4(qw, sb + t8 * (8 * KPU * 4) + laneK + 64);
            float c4[4] = {0.f, 0.f, 0.f, 0.f};
            mma_f16(c4, aq[0], qv[0], qv[1]);
            mma_f16(c4, aq[1], qv[2], qv[3]);
            mma_f16(c4, aq[2], qw[0], qw[1]);
            mma_f16(c4, aq[3], qw[2], qw[3]);

            float2 f0 = __half22float2(*reinterpret_cast<__half2*>(&ef.x));
            float2 f1 = __half22float2(*reinterpret_cast<__half2*>(&ef.y));
            float e0 = __expf(c4[0] + f0.x);
            float e1 = __expf(c4[1] + f0.y);
            float e2 = __expf(c4[2] + f1.x);
            float e3 = __expf(c4[3] + f1.y);
            l0 += e0 + e1;
            l1 += e2 + e3;
            uint2 st;
            st.x = packh2(e0, e1);
            st.y = packh2(e2, e3);
            scrW[(ch * 16 + t8) * 32] = st;
        }
        __syncthreads();
    }

    l0 += __shfl_xor_sync(0xffffffffu, l0, 1);
    l0 += __shfl_xor_sync(0xffffffffu, l0, 2);
    l1 += __shfl_xor_sync(0xffffffffu, l1, 1);
    l1 += __shfl_xor_sync(0xffffffffu, l1, 2);

    if (tg == 0) {
        g_linv[bh * SB + qg * 16 + g]     = 1.f / l0;
        g_linv[bh * SB + qg * 16 + g + 8] = 1.f / l1;
    }
    GDC_LAUNCH();   // e scratch + g_linv visible to pass2 after its wait
}

// ---------------------------------------------------------------------------
// Kernel 3: pass 2 — attention = e/l (fp32, STG.128 via quad shuffles);
// O = (sum e*V)/l via mma. PSS dependent of pass1: V-chunk prelude overlaps.
// ---------------------------------------------------------------------------
__global__ __launch_bounds__(256, 4) void k_pass2(
    float* __restrict__ out)
{
    __shared__ unsigned Bu[2][128 * KPU];

    const int tid  = threadIdx.x;
    const int warp = tid >> 5;
    const int lane = tid & 31;
    const int g    = lane >> 2;
    const int tg   = lane & 3;

    const int bh = blockIdx.x >> 3;
    const int q8 = blockIdx.x & 7;
    const int qg = q8 * 8 + warp;
    const int wb = warp * 16;

    const __half* Vh = g_kv + (size_t)(64 + bh) * (SB * DD);
    float* attnW = out + OUT_ELEMS + ((size_t)bh * SB + q8 * 128 + wb) * SB;
    float* outW  = out + ((size_t)bh * SB + q8 * 128 + wb) * DD;
    uint2* scrW  = reinterpret_cast<uint2*>(g_scr)
                 + ((size_t)bh * 64 + qg) * 4096 + lane;

    const unsigned sB0 = (unsigned)__cvta_generic_to_shared(&Bu[0][0]);
    const unsigned sB1 = sB0 + 128 * KPU * 4;

    auto load_chunk = [&](unsigned sbuf, const __half* src) {
#pragma unroll
        for (int j = 0; j < 4; j++) {
            int i = tid + j * 256;
            int r = i >> 3, u = i & 7;
            cpa16(sbuf + r * (KPU * 4) + u * 16, src + r * 64 + u * 8);
        }
    };

    // prelude: V chunk 0 (written by k_cvt, complete since before pass1 ran)
    load_chunk(sB0, Vh);
    CPA_COMMIT();

    GDC_WAIT();   // pass1 writes (e scratch, g_linv) now visible

    const float r0 = g_linv[bh * SB + qg * 16 + g];
    const float r1 = g_linv[bh * SB + qg * 16 + g + 8];

    float oc[8][4];
#pragma unroll
    for (int dt = 0; dt < 8; dt++)
#pragma unroll
        for (int j = 0; j < 4; j++) oc[dt][j] = 0.f;

    const unsigned laneV = ((lane & 7) + 8 * ((lane >> 3) & 1)) * (KPU * 4)
                         + (lane >> 4) * 16;
    const int srcA = (lane & ~3) | ((2 * tg) & 3);
    const int srcB = (lane & ~3) | ((2 * tg + 1) & 3);

    for (int ch = 0; ch < 8; ++ch) {
        if (ch < 7) {
            load_chunk((ch & 1) ? sB0 : sB1, Vh + (size_t)(ch + 1) * 8192);
            CPA_COMMIT();
            CPA_WAIT1();
        } else {
            CPA_WAIT0();
        }
        __syncthreads();

        const unsigned sb = (ch & 1) ? sB1 : sB0;
        uint2 pf[2][2];
#pragma unroll
        for (int p = 0; p < 2; p++) {
            pf[p][0] = __ldcs(&scrW[(ch * 16 + 2 * p) * 32]);
            pf[p][1] = __ldcs(&scrW[(ch * 16 + 2 * p + 1) * 32]);
        }

#pragma unroll
        for (int kg = 0; kg < 8; kg++) {
            uint2 ef0 = pf[kg & 1][0];
            uint2 ef1 = pf[kg & 1][1];
            if (kg < 6) {
                pf[kg & 1][0] = __ldcs(&scrW[(ch * 16 + 2 * kg + 4) * 32]);
                pf[kg & 1][1] = __ldcs(&scrW[(ch * 16 + 2 * kg + 5) * 32]);
            }
            unsigned ap[4] = {ef0.x, ef0.y, ef1.x, ef1.y};

            {   // attention stores: quad-shuffled into float4 (16 cols/row)
                int n0 = ch * 128 + kg * 16;
                // row g
                unsigned aL = __shfl_sync(0xffffffffu, ef0.x, srcA);
                unsigned bL = __shfl_sync(0xffffffffu, ef0.x, srcB);
                unsigned aH = __shfl_sync(0xffffffffu, ef1.x, srcA);
                unsigned bH = __shfl_sync(0xffffffffu, ef1.x, srcB);
                unsigned pa = (tg < 2) ? aL : aH;
                unsigned pb = (tg < 2) ? bL : bH;
                float2 fa = __half22float2(*reinterpret_cast<__half2*>(&pa));
                float2 fb = __half22float2(*reinterpret_cast<__half2*>(&pb));
                __stcs(reinterpret_cast<float4*>(attnW + (size_t)g * SB + n0 + 4 * tg),
                       make_float4(fa.x * r0, fa.y * r0, fb.x * r0, fb.y * r0));
                // row g+8
                aL = __shfl_sync(0xffffffffu, ef0.y, srcA);
                bL = __shfl_sync(0xffffffffu, ef0.y, srcB);
                aH = __shfl_sync(0xffffffffu, ef1.y, srcA);
                bH = __shfl_sync(0xffffffffu, ef1.y, srcB);
                pa = (tg < 2) ? aL : aH;
                pb = (tg < 2) ? bL : bH;
                fa = __half22float2(*reinterpret_cast<__half2*>(&pa));
                fb = __half22float2(*reinterpret_cast<__half2*>(&pb));
                __stcs(reinterpret_cast<float4*>(attnW + (size_t)(g + 8) * SB + n0 + 4 * tg),
                       make_float4(fa.x * r1, fa.y * r1, fb.x * r1, fb.y * r1));
            }

#pragma unroll
            for (int dp2 = 0; dp2 < 4; dp2++) {
                unsigned v[4];
                ldsm4t(v, sb + kg * (16 * KPU * 4) + laneV + dp2 * 32);
                mma_f16(oc[dp2 * 2],     ap, v[0], v[1]);
                mma_f16(oc[dp2 * 2 + 1], ap, v[2], v[3]);
            }
        }
        __syncthreads();
    }

#pragma unroll
    for (int dt = 0; dt < 8; dt++) {
        int col = dt * 8 + tg * 2;
        *reinterpret_cast<float2*>(outW + (size_t)g * DD + col) =
            make_float2(oc[dt][0] * r0, oc[dt][1] * r0);
        *reinterpret_cast<float2*>(outW + (size_t)(g + 8) * DD + col) =
            make_float2(oc[dt][2] * r1, oc[dt][3] * r1);
    }
}

// ---------------------------------------------------------------------------
// Launch: default stream only; PDL (programmatic stream serialization)
// provides k_cvt||k_bias overlap and boundary smoothing. No allocations.
// ---------------------------------------------------------------------------
template <typename F, typename... Args>
static void launch_pss(F func, dim3 grid, dim3 block, Args... args)
{
    cudaLaunchConfig_t cfg = {};
    cfg.gridDim  = grid;
    cfg.blockDim = block;
    cfg.stream   = 0;
    cudaLaunchAttribute attr[1];
    attr[0].id = cudaLaunchAttributeProgrammaticStreamSerialization;
    attr[0].val.programmaticStreamSerializationAllowed = 1;
    cfg.attrs    = attr;
    cfg.numAttrs = 1;
    cudaLaunchKernelEx(&cfg, func, args...);
}

extern "C" void kernel_launch(void* const* d_in, const int* in_sizes, int n_in,
                              void* d_out, int out_size)
{
    const float* Q    = (const float*)d_in[0];
    const float* K    = (const float*)d_in[1];
    const float* V    = (const float*)d_in[2];
    const float* dtw  = (const float*)d_in[3];
    const int*   mask = (const int*)d_in[4];
    const float* W    = (const float*)d_in[5];
    const float* bvec = (const float*)d_in[6];
    float*       out  = (float*)d_out;

    k_cvt<<<CVT_GRID, 256>>>(K, V);                       // triggers at start
    launch_pss(k_bias, dim3(4096), dim3(256), dtw, mask, W, bvec);
    launch_pss(k_pass1, dim3(BB * HH * (SB / 128)), dim3(256), Q);
    launch_pss(k_pass2, dim3(BB * HH * (SB / 128)), dim3(256), out);
}